// round 9
// baseline (speedup 1.0000x reference)
#include <cuda_runtime.h>
#include <cuda_bf16.h>
#include <cstdint>
#include <math.h>

// ---------------- problem constants ----------------
#define T_TOK 4096      // B*S tokens
#define D_K   4096      // d_in
#define KAUG  4224      // d_in + E*R augmented K
#define D_O   4096      // d_out
#define NEXP  8
#define ELCOL 128       // E*R
#define SCALING 2.0f

// ---------------- scratch (device globals; no allocation allowed) ----------------
__device__ __align__(256) __nv_bfloat16 g_XA_hi[(size_t)T_TOK * KAUG];
__device__ __align__(256) __nv_bfloat16 g_XA_lo[(size_t)T_TOK * KAUG];
__device__ __align__(256) __nv_bfloat16 g_WB_hi[(size_t)D_O * KAUG];
__device__ __align__(256) __nv_bfloat16 g_WB_lo[(size_t)D_O * KAUG];
__device__ __align__(256) __nv_bfloat16 g_LA_hi[(size_t)ELCOL * KAUG];
__device__ __align__(256) __nv_bfloat16 g_LA_lo[(size_t)ELCOL * KAUG];
__device__ __align__(256) float g_logits[T_TOK * NEXP];
__device__ __align__(256) float g_low[(size_t)T_TOK * ELCOL];

// ---------------- helpers ----------------
__device__ __forceinline__ uint32_t smem_u32(const void* p) {
    uint32_t a;
    asm("{ .reg .u64 t; cvta.to.shared.u64 t, %1; cvt.u32.u64 %0, t; }"
        : "=r"(a) : "l"(p));
    return a;
}

__device__ __forceinline__ void cpasync16(uint32_t dst, const void* src) {
    asm volatile("cp.async.cg.shared.global [%0], [%1], 16;" :: "r"(dst), "l"(src) : "memory");
}

// SW128: for byte offsets with 128B rows this is seg16 ^= (row & 7)
#define SW128(o) ((o) ^ ((((uint32_t)(o)) >> 3) & 0x70u))

__device__ __forceinline__ void ldm_x4(uint32_t& r0, uint32_t& r1, uint32_t& r2, uint32_t& r3,
                                       uint32_t addr) {
    asm volatile("ldmatrix.sync.aligned.m8n8.x4.shared.b16 {%0,%1,%2,%3}, [%4];"
                 : "=r"(r0), "=r"(r1), "=r"(r2), "=r"(r3) : "r"(addr));
}

__device__ __forceinline__ void mma16816(float& d0, float& d1, float& d2, float& d3,
                                         uint32_t a0, uint32_t a1, uint32_t a2, uint32_t a3,
                                         uint32_t b0, uint32_t b1) {
    asm volatile(
        "mma.sync.aligned.m16n8k16.row.col.f32.bf16.bf16.f32 "
        "{%0,%1,%2,%3}, {%4,%5,%6,%7}, {%8,%9}, {%0,%1,%2,%3};"
        : "+f"(d0), "+f"(d1), "+f"(d2), "+f"(d3)
        : "r"(a0), "r"(a1), "r"(a2), "r"(a3), "r"(b0), "r"(b1));
}

// ---------------- convert kernels ----------------
__device__ __forceinline__ void split_store(float v, __nv_bfloat16* hi, __nv_bfloat16* lo, size_t idx) {
    __nv_bfloat16 h = __float2bfloat16(v);
    float r = v - __bfloat162float(h);
    hi[idx] = h;
    lo[idx] = __float2bfloat16(r);
}

__global__ void k_convert_x(const float* __restrict__ x) {
    size_t stride = (size_t)gridDim.x * blockDim.x;
    for (size_t i = (size_t)blockIdx.x * blockDim.x + threadIdx.x;
         i < (size_t)T_TOK * D_K; i += stride) {
        size_t t = i >> 12, k = i & 4095;
        split_store(x[i], g_XA_hi, g_XA_lo, t * KAUG + k);
    }
}

__global__ void k_convert_w(const float* __restrict__ bw, const float* __restrict__ lb) {
    size_t stride = (size_t)gridDim.x * blockDim.x;
    const size_t N1 = (size_t)D_O * D_K;           // base_w
    const size_t N2 = (size_t)NEXP * D_O * 16;     // lora_B [E, O, R]
    for (size_t i = (size_t)blockIdx.x * blockDim.x + threadIdx.x;
         i < N1 + N2; i += stride) {
        if (i < N1) {
            size_t o = i >> 12, k = i & 4095;
            split_store(bw[i], g_WB_hi, g_WB_lo, o * KAUG + k);
        } else {
            size_t j = i - N1;
            size_t e = j >> 16;            // 4096*16 per expert
            size_t rem = j & 65535;
            size_t o = rem >> 4, r = rem & 15;
            split_store(lb[j], g_WB_hi, g_WB_lo, o * KAUG + D_K + e * 16 + r);
        }
    }
}

__global__ void k_convert_la(const float* __restrict__ la) {
    size_t stride = (size_t)gridDim.x * blockDim.x;
    for (size_t i = (size_t)blockIdx.x * blockDim.x + threadIdx.x;
         i < (size_t)ELCOL * D_K; i += stride) {
        size_t row = i >> 12, k = i & 4095;
        split_store(la[i], g_LA_hi, g_LA_lo, row * KAUG + k);
    }
}

// ---------------- gate: exact fp32 logits, one warp per token ----------------
__global__ void k_gate(const float* __restrict__ x, const float* __restrict__ gw) {
    int warp = (int)((blockIdx.x * blockDim.x + threadIdx.x) >> 5);
    int lane = threadIdx.x & 31;
    if (warp >= T_TOK) return;
    const float4* xp = (const float4*)(x + (size_t)warp * D_K);
    float acc[NEXP];
#pragma unroll
    for (int e = 0; e < NEXP; e++) acc[e] = 0.f;
    for (int j = 0; j < 32; j++) {
        int idx = j * 32 + lane;
        float4 xv = xp[idx];
#pragma unroll
        for (int e = 0; e < NEXP; e++) {
            float4 gv = ((const float4*)(gw + (size_t)e * D_K))[idx];
            acc[e] += xv.x * gv.x + xv.y * gv.y + xv.z * gv.z + xv.w * gv.w;
        }
    }
#pragma unroll
    for (int e = 0; e < NEXP; e++) {
        float v = acc[e];
#pragma unroll
        for (int o = 16; o; o >>= 1) v += __shfl_xor_sync(0xffffffffu, v, o);
        if (lane == 0) g_logits[warp * NEXP + e] = v;
    }
}

// ---------------- routing: top-2 + softmax, build augmented U columns ----------------
__global__ void k_route() {
    int t = (int)((blockIdx.x * blockDim.x + threadIdx.x) >> 5);
    int lane = threadIdx.x & 31;
    if (t >= T_TOK) return;
    int i1 = 0, i2 = 0;
    float w1 = 0.f, w2 = 0.f;
    if (lane == 0) {
        float m1 = -1e30f, m2 = -1e30f;
#pragma unroll
        for (int e = 0; e < NEXP; e++) {
            float v = g_logits[t * NEXP + e];
            if (v > m1) { m2 = m1; i2 = i1; m1 = v; i1 = e; }
            else if (v > m2) { m2 = v; i2 = e; }
        }
        float s2 = expf(m2 - m1);
        w1 = 1.f / (1.f + s2);
        w2 = s2 * w1;
    }
    i1 = __shfl_sync(0xffffffffu, i1, 0);
    i2 = __shfl_sync(0xffffffffu, i2, 0);
    w1 = __shfl_sync(0xffffffffu, w1, 0);
    w2 = __shfl_sync(0xffffffffu, w2, 0);
#pragma unroll
    for (int j = 0; j < 4; j++) {
        int col = j * 32 + lane;
        int e = col >> 4;
        float wv = (e == i1) ? SCALING * w1 : (e == i2) ? SCALING * w2 : 0.f;
        float v = wv * g_low[(size_t)t * ELCOL + col];
        split_store(v, g_XA_hi, g_XA_lo, (size_t)t * KAUG + D_K + col);
    }
}

// ---------------- split-bf16 mma.sync GEMM ----------------
// C[m, n] = sum_k (Ahi+Alo)[m,k]*(Bhi+Blo)[n,k]  (hi*hi + hi*lo + lo*hi), + bias[n]
// A, B K-major (ld = KAUG). CTA tile 128x128, BK=64, 3-stage cp.async pipeline.
#define STAGES 3
#define BK 64
#define STAGE_BYTES 65536           // Ahi|Alo|Bhi|Blo, each 128 rows x 128B
#define A_HI_OFF 0
#define A_LO_OFF 16384
#define B_HI_OFF 32768
#define B_LO_OFF 49152
#define SMEM_TOTAL (STAGES * STAGE_BYTES)   // 192 KB (epilogue reuses)
#define EPI_PITCH 132

struct GemmPtrs {
    const __nv_bfloat16 *Ahi, *Alo, *Bhi, *Blo;
};

__device__ __forceinline__ void load_chunk(
    uint32_t sb, int tid, int m0, int n0, int c, const GemmPtrs p)
{
    const uint32_t base = sb + (uint32_t)((c % STAGES) * STAGE_BYTES);
    const size_t kb = (size_t)c * BK;
#pragma unroll
    for (int pass = 0; pass < 4; pass++) {
        const int i = pass * 256 + tid;       // 0..1023
        const int row = i >> 3;
        const int seg = i & 7;
        const uint32_t so = SW128((uint32_t)(row * 128 + seg * 16));
        const size_t ao = (size_t)(m0 + row) * KAUG + kb + seg * 8;
        const size_t bo = (size_t)(n0 + row) * KAUG + kb + seg * 8;
        cpasync16(base + A_HI_OFF + so, p.Ahi + ao);
        cpasync16(base + A_LO_OFF + so, p.Alo + ao);
        cpasync16(base + B_HI_OFF + so, p.Bhi + bo);
        cpasync16(base + B_LO_OFF + so, p.Blo + bo);
    }
}

__global__ void __launch_bounds__(256, 1)
gemm_split(const __nv_bfloat16* __restrict__ Ahi, const __nv_bfloat16* __restrict__ Alo,
           const __nv_bfloat16* __restrict__ Bhi, const __nv_bfloat16* __restrict__ Blo,
           float* __restrict__ C, const float* __restrict__ bias,
           int nChunks, int ldC)
{
    extern __shared__ char smem[];
    const uint32_t sb = smem_u32(smem);
    const int tid = threadIdx.x;
    const int wid = tid >> 5;
    const int lane = tid & 31;
    const int wm = wid & 1;          // 2 warp rows (64 m each)
    const int wn = wid >> 1;         // 4 warp cols (32 n each)
    const int m0 = blockIdx.x * 128;
    const int n0 = blockIdx.y * 128;
    GemmPtrs p{Ahi, Alo, Bhi, Blo};

    float acc[4][4][4];              // [mtile][ntile][frag]
#pragma unroll
    for (int i = 0; i < 4; i++)
#pragma unroll
        for (int j = 0; j < 4; j++)
#pragma unroll
            for (int k = 0; k < 4; k++) acc[i][j][k] = 0.f;

    // per-lane ldmatrix row/seg components (within a 16-row tile)
    const int a_row = lane & 15;                 // A: rows 0-15
    const int a_seg = lane >> 4;                 // A: k 16B half
    const int b_row = (lane & 7) + ((lane >> 4) << 3);   // B: n row 0-15
    const int b_seg = (lane >> 3) & 1;                   // B: k 16B half

    // prologue: stages 0..STAGES-2
#pragma unroll
    for (int c = 0; c < STAGES - 1; c++) {
        load_chunk(sb, tid, m0, n0, c, p);
        asm volatile("cp.async.commit_group;" ::: "memory");
    }

    for (int c = 0; c < nChunks; c++) {
        asm volatile("cp.async.wait_group %0;" :: "n"(STAGES - 2) : "memory");
        __syncthreads();

        // issue next loads first (overlap with compute)
        if (c + STAGES - 1 < nChunks)
            load_chunk(sb, tid, m0, n0, c + STAGES - 1, p);
        asm volatile("cp.async.commit_group;" ::: "memory");

        const uint32_t base = sb + (uint32_t)((c % STAGES) * STAGE_BYTES);
#pragma unroll
        for (int ks = 0; ks < BK / 16; ks++) {
            uint32_t ah[4][4], al[4][4];
#pragma unroll
            for (int mt = 0; mt < 4; mt++) {
                const int row = wm * 64 + mt * 16 + a_row;
                const uint32_t so = SW128((uint32_t)(row * 128 + (ks * 2 + a_seg) * 16));
                ldm_x4(ah[mt][0], ah[mt][1], ah[mt][2], ah[mt][3], base + A_HI_OFF + so);
                ldm_x4(al[mt][0], al[mt][1], al[mt][2], al[mt][3], base + A_LO_OFF + so);
            }
            uint32_t bh[2][4], bl[2][4];
#pragma unroll
            for (int pr = 0; pr < 2; pr++) {
                const int row = wn * 32 + pr * 16 + b_row;
                const uint32_t so = SW128((uint32_t)(row * 128 + (ks * 2 + b_seg) * 16));
                ldm_x4(bh[pr][0], bh[pr][1], bh[pr][2], bh[pr][3], base + B_HI_OFF + so);
                ldm_x4(bl[pr][0], bl[pr][1], bl[pr][2], bl[pr][3], base + B_LO_OFF + so);
            }
#pragma unroll
            for (int mt = 0; mt < 4; mt++) {
#pragma unroll
                for (int nt = 0; nt < 4; nt++) {
                    const int pr = nt >> 1, rb = (nt & 1) * 2;
                    float* d = acc[mt][nt];
                    mma16816(d[0], d[1], d[2], d[3],
                             ah[mt][0], ah[mt][1], ah[mt][2], ah[mt][3],
                             bh[pr][rb], bh[pr][rb + 1]);
                    mma16816(d[0], d[1], d[2], d[3],
                             ah[mt][0], ah[mt][1], ah[mt][2], ah[mt][3],
                             bl[pr][rb], bl[pr][rb + 1]);
                    mma16816(d[0], d[1], d[2], d[3],
                             al[mt][0], al[mt][1], al[mt][2], al[mt][3],
                             bh[pr][rb], bh[pr][rb + 1]);
                }
            }
        }
    }
    __syncthreads();

    // epilogue: frags -> smem (padded) -> coalesced global with fused bias
    float* smf = (float*)smem;
#pragma unroll
    for (int mt = 0; mt < 4; mt++) {
#pragma unroll
        for (int nt = 0; nt < 4; nt++) {
            const int row = wm * 64 + mt * 16 + (lane >> 2);
            const int col = wn * 32 + nt * 8 + (lane & 3) * 2;
            smf[row * EPI_PITCH + col]           = acc[mt][nt][0];
            smf[row * EPI_PITCH + col + 1]       = acc[mt][nt][1];
            smf[(row + 8) * EPI_PITCH + col]     = acc[mt][nt][2];
            smf[(row + 8) * EPI_PITCH + col + 1] = acc[mt][nt][3];
        }
    }
    __syncthreads();
    for (int i = tid; i < 128 * 128; i += 256) {
        const int r = i >> 7, col = i & 127;
        const float bv = bias ? bias[n0 + col] : 0.f;
        C[(size_t)(m0 + r) * ldC + n0 + col] = smf[r * EPI_PITCH + col] + bv;
    }
}

// ---------------- launch ----------------
extern "C" void kernel_launch(void* const* d_in, const int* in_sizes, int n_in,
                              void* d_out, int out_size) {
    const float* x  = (const float*)d_in[0];
    const float* gw = (const float*)d_in[1];
    const float* bw = (const float*)d_in[2];
    const float* bb = (const float*)d_in[3];
    const float* la = (const float*)d_in[4];
    const float* lb = (const float*)d_in[5];
    float* out = (float*)d_out;

    void *p_xahi, *p_xalo, *p_wbhi, *p_wblo, *p_lahi, *p_lalo, *p_low;
    cudaGetSymbolAddress(&p_xahi, g_XA_hi);
    cudaGetSymbolAddress(&p_xalo, g_XA_lo);
    cudaGetSymbolAddress(&p_wbhi, g_WB_hi);
    cudaGetSymbolAddress(&p_wblo, g_WB_lo);
    cudaGetSymbolAddress(&p_lahi, g_LA_hi);
    cudaGetSymbolAddress(&p_lalo, g_LA_lo);
    cudaGetSymbolAddress(&p_low,  g_low);

    cudaFuncSetAttribute(gemm_split, cudaFuncAttributeMaxDynamicSharedMemorySize, SMEM_TOTAL);

    k_convert_x<<<4096, 256>>>(x);
    k_convert_w<<<4096, 256>>>(bw, lb);
    k_convert_la<<<512, 256>>>(la);
    k_gate<<<512, 256>>>(x, gw);

    // pass 1: low = X @ lora_A_cat^T   (M=4096, N=128, K=4096 -> 64 chunks)
    gemm_split<<<dim3(32, 1), 256, SMEM_TOTAL>>>(
        (const __nv_bfloat16*)p_xahi, (const __nv_bfloat16*)p_xalo,
        (const __nv_bfloat16*)p_lahi, (const __nv_bfloat16*)p_lalo,
        (float*)p_low, nullptr, 64, ELCOL);

    k_route<<<1024, 128>>>();

    // pass 2: out = [X|U] @ [W|loraB]^T + b  (M=4096, N=4096, K=4224 -> 66 chunks)
    gemm_split<<<dim3(32, 32), 256, SMEM_TOTAL>>>(
        (const __nv_bfloat16*)p_xahi, (const __nv_bfloat16*)p_xalo,
        (const __nv_bfloat16*)p_wbhi, (const __nv_bfloat16*)p_wblo,
        out, bb, 66, D_O);
}

// round 12
// speedup vs baseline: 1.1135x; 1.1135x over previous
#include <cuda_runtime.h>
#include <cuda_bf16.h>
#include <cstdint>
#include <math.h>

// ---------------- problem constants ----------------
#define T_TOK 4096      // B*S tokens
#define D_K   4096      // d_in
#define KAUG  4224      // d_in + E*R augmented K
#define D_O   4096      // d_out
#define NEXP  8
#define ELCOL 128       // E*R
#define SCALING 2.0f
#define KSPLIT1 4       // pass-1 split-K factor

// ---------------- scratch (device globals; no allocation allowed) ----------------
__device__ __align__(256) __nv_bfloat16 g_XA_hi[(size_t)T_TOK * KAUG];
__device__ __align__(256) __nv_bfloat16 g_XA_lo[(size_t)T_TOK * KAUG];
__device__ __align__(256) __nv_bfloat16 g_WB_hi[(size_t)D_O * KAUG];
__device__ __align__(256) __nv_bfloat16 g_WB_lo[(size_t)D_O * KAUG];
__device__ __align__(256) __nv_bfloat16 g_LA_hi[(size_t)ELCOL * KAUG];
__device__ __align__(256) __nv_bfloat16 g_LA_lo[(size_t)ELCOL * KAUG];
__device__ __align__(256) float g_logits[T_TOK * NEXP];
__device__ __align__(256) float g_lowp[(size_t)KSPLIT1 * T_TOK * ELCOL];

// ---------------- helpers ----------------
__device__ __forceinline__ uint32_t smem_u32(const void* p) {
    uint32_t a;
    asm("{ .reg .u64 t; cvta.to.shared.u64 t, %1; cvt.u32.u64 %0, t; }"
        : "=r"(a) : "l"(p));
    return a;
}

__device__ __forceinline__ void cpasync16(uint32_t dst, const void* src) {
    asm volatile("cp.async.cg.shared.global [%0], [%1], 16;" :: "r"(dst), "l"(src) : "memory");
}

// SW128: for byte offsets with 128B rows this is seg16 ^= (row & 7)
#define SW128(o) ((o) ^ ((((uint32_t)(o)) >> 3) & 0x70u))

__device__ __forceinline__ void ldm_x4(uint32_t& r0, uint32_t& r1, uint32_t& r2, uint32_t& r3,
                                       uint32_t addr) {
    asm volatile("ldmatrix.sync.aligned.m8n8.x4.shared.b16 {%0,%1,%2,%3}, [%4];"
                 : "=r"(r0), "=r"(r1), "=r"(r2), "=r"(r3) : "r"(addr));
}

__device__ __forceinline__ void mma16816(float& d0, float& d1, float& d2, float& d3,
                                         uint32_t a0, uint32_t a1, uint32_t a2, uint32_t a3,
                                         uint32_t b0, uint32_t b1) {
    asm volatile(
        "mma.sync.aligned.m16n8k16.row.col.f32.bf16.bf16.f32 "
        "{%0,%1,%2,%3}, {%4,%5,%6,%7}, {%8,%9}, {%0,%1,%2,%3};"
        : "+f"(d0), "+f"(d1), "+f"(d2), "+f"(d3)
        : "r"(a0), "r"(a1), "r"(a2), "r"(a3), "r"(b0), "r"(b1));
}

// ---------------- convert kernels (vectorized: float4 in, 8B bf16x4 out) ----------------
__device__ __forceinline__ void split_store(float v, __nv_bfloat16* hi, __nv_bfloat16* lo, size_t idx) {
    __nv_bfloat16 h = __float2bfloat16(v);
    float r = v - __bfloat162float(h);
    hi[idx] = h;
    lo[idx] = __float2bfloat16(r);
}

__device__ __forceinline__ void split4_store(float4 v, __nv_bfloat16* hi, __nv_bfloat16* lo, size_t idx) {
    __nv_bfloat162 h01, h23, l01, l23;
    h01.x = __float2bfloat16(v.x); h01.y = __float2bfloat16(v.y);
    h23.x = __float2bfloat16(v.z); h23.y = __float2bfloat16(v.w);
    l01.x = __float2bfloat16(v.x - __bfloat162float(h01.x));
    l01.y = __float2bfloat16(v.y - __bfloat162float(h01.y));
    l23.x = __float2bfloat16(v.z - __bfloat162float(h23.x));
    l23.y = __float2bfloat16(v.w - __bfloat162float(h23.y));
    uint2 H, L;
    H.x = *reinterpret_cast<uint32_t*>(&h01); H.y = *reinterpret_cast<uint32_t*>(&h23);
    L.x = *reinterpret_cast<uint32_t*>(&l01); L.y = *reinterpret_cast<uint32_t*>(&l23);
    *reinterpret_cast<uint2*>(hi + idx) = H;
    *reinterpret_cast<uint2*>(lo + idx) = L;
}

__global__ void k_convert_x(const float* __restrict__ x) {
    size_t stride = (size_t)gridDim.x * blockDim.x;
    const size_t N4 = (size_t)T_TOK * D_K / 4;
    for (size_t i = (size_t)blockIdx.x * blockDim.x + threadIdx.x; i < N4; i += stride) {
        size_t base = i * 4;
        size_t t = base >> 12, k = base & 4095;
        split4_store(((const float4*)x)[i], g_XA_hi, g_XA_lo, t * KAUG + k);
    }
}

__global__ void k_convert_w(const float* __restrict__ bw, const float* __restrict__ lb) {
    size_t stride = (size_t)gridDim.x * blockDim.x;
    const size_t N1_4 = (size_t)D_O * D_K / 4;             // base_w in float4s
    const size_t N2_4 = (size_t)NEXP * D_O * 16 / 4;       // lora_B [E, O, R] in float4s
    for (size_t i = (size_t)blockIdx.x * blockDim.x + threadIdx.x;
         i < N1_4 + N2_4; i += stride) {
        if (i < N1_4) {
            size_t base = i * 4;
            size_t o = base >> 12, k = base & 4095;
            split4_store(((const float4*)bw)[i], g_WB_hi, g_WB_lo, o * KAUG + k);
        } else {
            size_t j = (i - N1_4) * 4;                     // element index in lora_B
            size_t e = j >> 16;                            // 4096*16 per expert
            size_t rem = j & 65535;
            size_t o = rem >> 4, r = rem & 15;             // r multiple of 4
            split4_store(((const float4*)lb)[i - N1_4 + 0] /* = lb[j..j+3] */,
                         g_WB_hi, g_WB_lo, o * KAUG + D_K + e * 16 + r);
        }
    }
}

__global__ void k_convert_la(const float* __restrict__ la) {
    size_t stride = (size_t)gridDim.x * blockDim.x;
    const size_t N4 = (size_t)ELCOL * D_K / 4;
    for (size_t i = (size_t)blockIdx.x * blockDim.x + threadIdx.x; i < N4; i += stride) {
        size_t base = i * 4;
        size_t row = base >> 12, k = base & 4095;
        split4_store(((const float4*)la)[i], g_LA_hi, g_LA_lo, row * KAUG + k);
    }
}

// ---------------- gate: exact fp32 logits, one warp per token, 2-way ILP ----------------
__global__ void k_gate(const float* __restrict__ x, const float* __restrict__ gw) {
    int warp = (int)((blockIdx.x * blockDim.x + threadIdx.x) >> 5);
    int lane = threadIdx.x & 31;
    if (warp >= T_TOK) return;
    const float4* xp = (const float4*)(x + (size_t)warp * D_K);
    const float4* gp = (const float4*)gw;
    float acc0[NEXP], acc1[NEXP];
#pragma unroll
    for (int e = 0; e < NEXP; e++) { acc0[e] = 0.f; acc1[e] = 0.f; }
    for (int j = 0; j < 32; j += 2) {
        int i0 = j * 32 + lane;
        int i1 = i0 + 32;
        float4 xv0 = xp[i0];
        float4 xv1 = xp[i1];
#pragma unroll
        for (int e = 0; e < NEXP; e++) {
            float4 g0 = gp[e * 1024 + i0];
            float4 g1 = gp[e * 1024 + i1];
            acc0[e] += xv0.x * g0.x + xv0.y * g0.y + xv0.z * g0.z + xv0.w * g0.w;
            acc1[e] += xv1.x * g1.x + xv1.y * g1.y + xv1.z * g1.z + xv1.w * g1.w;
        }
    }
#pragma unroll
    for (int e = 0; e < NEXP; e++) {
        float v = acc0[e] + acc1[e];
#pragma unroll
        for (int o = 16; o; o >>= 1) v += __shfl_xor_sync(0xffffffffu, v, o);
        if (lane == 0) g_logits[warp * NEXP + e] = v;
    }
}

// ---------------- routing: top-2 + softmax, reduce split-K partials, build U ----------------
__global__ void k_route() {
    int t = (int)((blockIdx.x * blockDim.x + threadIdx.x) >> 5);
    int lane = threadIdx.x & 31;
    if (t >= T_TOK) return;
    int i1 = 0, i2 = 0;
    float w1 = 0.f, w2 = 0.f;
    if (lane == 0) {
        float m1 = -1e30f, m2 = -1e30f;
#pragma unroll
        for (int e = 0; e < NEXP; e++) {
            float v = g_logits[t * NEXP + e];
            if (v > m1) { m2 = m1; i2 = i1; m1 = v; i1 = e; }
            else if (v > m2) { m2 = v; i2 = e; }
        }
        float s2 = expf(m2 - m1);
        w1 = 1.f / (1.f + s2);
        w2 = s2 * w1;
    }
    i1 = __shfl_sync(0xffffffffu, i1, 0);
    i2 = __shfl_sync(0xffffffffu, i2, 0);
    w1 = __shfl_sync(0xffffffffu, w1, 0);
    w2 = __shfl_sync(0xffffffffu, w2, 0);
    const size_t PS = (size_t)T_TOK * ELCOL;
#pragma unroll
    for (int j = 0; j < 4; j++) {
        int col = j * 32 + lane;
        int e = col >> 4;
        float wv = (e == i1) ? SCALING * w1 : (e == i2) ? SCALING * w2 : 0.f;
        float low = 0.f;
#pragma unroll
        for (int pz = 0; pz < KSPLIT1; pz++)
            low += g_lowp[pz * PS + (size_t)t * ELCOL + col];
        split_store(wv * low, g_XA_hi, g_XA_lo, (size_t)t * KAUG + D_K + col);
    }
}

// ---------------- split-bf16 mma.sync GEMM ----------------
// C[m, n] = sum_k (Ahi+Alo)[m,k]*(Bhi+Blo)[n,k]  (hi*hi + hi*lo + lo*hi), + bias[n]
// A, B K-major (ld = KAUG). CTA tile 128x128, BK=64, 3-stage cp.async pipeline.
// blockIdx.z = split-K slice: chunks [z*nChunks, (z+1)*nChunks), C += z*strideZ.
#define STAGES 3
#define BK 64
#define STAGE_BYTES 65536           // Ahi|Alo|Bhi|Blo, each 128 rows x 128B
#define A_HI_OFF 0
#define A_LO_OFF 16384
#define B_HI_OFF 32768
#define B_LO_OFF 49152
#define SMEM_TOTAL (STAGES * STAGE_BYTES)   // 192 KB (epilogue reuses)
#define EPI_PITCH 132

struct GemmPtrs {
    const __nv_bfloat16 *Ahi, *Alo, *Bhi, *Blo;
};

__device__ __forceinline__ void load_chunk(
    uint32_t sb, int tid, int m0, int n0, int stage, size_t kb, const GemmPtrs p)
{
    const uint32_t base = sb + (uint32_t)(stage * STAGE_BYTES);
#pragma unroll
    for (int pass = 0; pass < 4; pass++) {
        const int i = pass * 256 + tid;       // 0..1023
        const int row = i >> 3;
        const int seg = i & 7;
        const uint32_t so = SW128((uint32_t)(row * 128 + seg * 16));
        const size_t ao = (size_t)(m0 + row) * KAUG + kb + seg * 8;
        const size_t bo = (size_t)(n0 + row) * KAUG + kb + seg * 8;
        cpasync16(base + A_HI_OFF + so, p.Ahi + ao);
        cpasync16(base + A_LO_OFF + so, p.Alo + ao);
        cpasync16(base + B_HI_OFF + so, p.Bhi + bo);
        cpasync16(base + B_LO_OFF + so, p.Blo + bo);
    }
}

__global__ void __launch_bounds__(256, 1)
gemm_split(const __nv_bfloat16* __restrict__ Ahi, const __nv_bfloat16* __restrict__ Alo,
           const __nv_bfloat16* __restrict__ Bhi, const __nv_bfloat16* __restrict__ Blo,
           float* __restrict__ C, const float* __restrict__ bias,
           int nChunks, int ldC, size_t strideZ)
{
    extern __shared__ char smem[];
    const uint32_t sb = smem_u32(smem);
    const int tid = threadIdx.x;
    const int wid = tid >> 5;
    const int lane = tid & 31;
    const int wm = wid & 1;          // 2 warp rows (64 m each)
    const int wn = wid >> 1;         // 4 warp cols (32 n each)
    const int m0 = blockIdx.x * 128;
    const int n0 = blockIdx.y * 128;
    const int kOff = blockIdx.z * nChunks;
    C += (size_t)blockIdx.z * strideZ;
    GemmPtrs p{Ahi, Alo, Bhi, Blo};

    float acc[4][4][4];              // [mtile][ntile][frag]
#pragma unroll
    for (int i = 0; i < 4; i++)
#pragma unroll
        for (int j = 0; j < 4; j++)
#pragma unroll
            for (int k = 0; k < 4; k++) acc[i][j][k] = 0.f;

    // per-lane ldmatrix row/seg components (within a 16-row tile)
    const int a_row = lane & 15;                 // A: rows 0-15
    const int a_seg = lane >> 4;                 // A: k 16B half
    const int b_row = (lane & 7) + ((lane >> 4) << 3);   // B: n row 0-15
    const int b_seg = (lane >> 3) & 1;                   // B: k 16B half

    // prologue: stages 0..STAGES-2
#pragma unroll
    for (int c = 0; c < STAGES - 1; c++) {
        load_chunk(sb, tid, m0, n0, c, (size_t)(kOff + c) * BK, p);
        asm volatile("cp.async.commit_group;" ::: "memory");
    }

    for (int c = 0; c < nChunks; c++) {
        asm volatile("cp.async.wait_group %0;" :: "n"(STAGES - 2) : "memory");
        __syncthreads();

        // issue next loads first (overlap with compute)
        if (c + STAGES - 1 < nChunks)
            load_chunk(sb, tid, m0, n0, (c + STAGES - 1) % STAGES,
                       (size_t)(kOff + c + STAGES - 1) * BK, p);
        asm volatile("cp.async.commit_group;" ::: "memory");

        const uint32_t base = sb + (uint32_t)((c % STAGES) * STAGE_BYTES);
#pragma unroll
        for (int ks = 0; ks < BK / 16; ks++) {
            uint32_t ah[4][4], al[4][4];
#pragma unroll
            for (int mt = 0; mt < 4; mt++) {
                const int row = wm * 64 + mt * 16 + a_row;
                const uint32_t so = SW128((uint32_t)(row * 128 + (ks * 2 + a_seg) * 16));
                ldm_x4(ah[mt][0], ah[mt][1], ah[mt][2], ah[mt][3], base + A_HI_OFF + so);
                ldm_x4(al[mt][0], al[mt][1], al[mt][2], al[mt][3], base + A_LO_OFF + so);
            }
            uint32_t bh[2][4], bl[2][4];
#pragma unroll
            for (int pr = 0; pr < 2; pr++) {
                const int row = wn * 32 + pr * 16 + b_row;
                const uint32_t so = SW128((uint32_t)(row * 128 + (ks * 2 + b_seg) * 16));
                ldm_x4(bh[pr][0], bh[pr][1], bh[pr][2], bh[pr][3], base + B_HI_OFF + so);
                ldm_x4(bl[pr][0], bl[pr][1], bl[pr][2], bl[pr][3], base + B_LO_OFF + so);
            }
#pragma unroll
            for (int mt = 0; mt < 4; mt++) {
#pragma unroll
                for (int nt = 0; nt < 4; nt++) {
                    const int pr = nt >> 1, rb = (nt & 1) * 2;
                    float* d = acc[mt][nt];
                    mma16816(d[0], d[1], d[2], d[3],
                             ah[mt][0], ah[mt][1], ah[mt][2], ah[mt][3],
                             bh[pr][rb], bh[pr][rb + 1]);
                    mma16816(d[0], d[1], d[2], d[3],
                             ah[mt][0], ah[mt][1], ah[mt][2], ah[mt][3],
                             bl[pr][rb], bl[pr][rb + 1]);
                    mma16816(d[0], d[1], d[2], d[3],
                             al[mt][0], al[mt][1], al[mt][2], al[mt][3],
                             bh[pr][rb], bh[pr][rb + 1]);
                }
            }
        }
    }
    __syncthreads();

    // epilogue: frags -> smem (padded) -> coalesced global with fused bias
    float* smf = (float*)smem;
#pragma unroll
    for (int mt = 0; mt < 4; mt++) {
#pragma unroll
        for (int nt = 0; nt < 4; nt++) {
            const int row = wm * 64 + mt * 16 + (lane >> 2);
            const int col = wn * 32 + nt * 8 + (lane & 3) * 2;
            smf[row * EPI_PITCH + col]           = acc[mt][nt][0];
            smf[row * EPI_PITCH + col + 1]       = acc[mt][nt][1];
            smf[(row + 8) * EPI_PITCH + col]     = acc[mt][nt][2];
            smf[(row + 8) * EPI_PITCH + col + 1] = acc[mt][nt][3];
        }
    }
    __syncthreads();
    for (int i = tid; i < 128 * 128; i += 256) {
        const int r = i >> 7, col = i & 127;
        const float bv = bias ? bias[n0 + col] : 0.f;
        C[(size_t)(m0 + r) * ldC + n0 + col] = smf[r * EPI_PITCH + col] + bv;
    }
}

// ---------------- launch ----------------
extern "C" void kernel_launch(void* const* d_in, const int* in_sizes, int n_in,
                              void* d_out, int out_size) {
    const float* x  = (const float*)d_in[0];
    const float* gw = (const float*)d_in[1];
    const float* bw = (const float*)d_in[2];
    const float* bb = (const float*)d_in[3];
    const float* la = (const float*)d_in[4];
    const float* lb = (const float*)d_in[5];
    float* out = (float*)d_out;

    void *p_xahi, *p_xalo, *p_wbhi, *p_wblo, *p_lahi, *p_lalo, *p_lowp;
    cudaGetSymbolAddress(&p_xahi, g_XA_hi);
    cudaGetSymbolAddress(&p_xalo, g_XA_lo);
    cudaGetSymbolAddress(&p_wbhi, g_WB_hi);
    cudaGetSymbolAddress(&p_wblo, g_WB_lo);
    cudaGetSymbolAddress(&p_lahi, g_LA_hi);
    cudaGetSymbolAddress(&p_lalo, g_LA_lo);
    cudaGetSymbolAddress(&p_lowp, g_lowp);

    cudaFuncSetAttribute(gemm_split, cudaFuncAttributeMaxDynamicSharedMemorySize, SMEM_TOTAL);

    k_convert_x<<<2048, 256>>>(x);
    k_convert_w<<<2048, 256>>>(bw, lb);
    k_convert_la<<<256, 256>>>(la);
    k_gate<<<512, 256>>>(x, gw);

    // pass 1: low = X @ lora_A_cat^T   (M=4096, N=128, K=4096; split-K x4 -> 128 CTAs)
    gemm_split<<<dim3(32, 1, KSPLIT1), 256, SMEM_TOTAL>>>(
        (const __nv_bfloat16*)p_xahi, (const __nv_bfloat16*)p_xalo,
        (const __nv_bfloat16*)p_lahi, (const __nv_bfloat16*)p_lalo,
        (float*)p_lowp, nullptr, 64 / KSPLIT1, ELCOL, (size_t)T_TOK * ELCOL);

    k_route<<<1024, 128>>>();

    // pass 2: out = [X|U] @ [W|loraB]^T + b  (M=4096, N=4096, K=4224 -> 66 chunks)
    gemm_split<<<dim3(32, 32, 1), 256, SMEM_TOTAL>>>(
        (const __nv_bfloat16*)p_xahi, (const __nv_bfloat16*)p_xalo,
        (const __nv_bfloat16*)p_wbhi, (const __nv_bfloat16*)p_wblo,
        out, bb, 66, D_O, 0);
}

// round 16
// speedup vs baseline: 1.5959x; 1.4332x over previous
#include <cuda_runtime.h>
#include <cuda_fp16.h>
#include <cstdint>
#include <math.h>

// ---------------- problem constants ----------------
#define T_TOK 4096      // B*S tokens
#define D_K   4096      // d_in
#define KAUG  4224      // d_in + E*R augmented K
#define D_O   4096      // d_out
#define NEXP  8
#define ELCOL 128       // E*R
#define SCALING 2.0f
#define KSPLIT1 4       // pass-1 split-K factor

// ---------------- scratch (device globals; no allocation allowed) ----------------
// A-side (tokens): fp16 hi + lo (2-term split, pair error ~2^-21)
// B-side (weights): single fp16 (error ~2^-11 RMS -> ~2e-4 global rel err)
__device__ __align__(256) __half g_XA_hi[(size_t)T_TOK * KAUG];
__device__ __align__(256) __half g_XA_lo[(size_t)T_TOK * KAUG];
__device__ __align__(256) __half g_WB[(size_t)D_O * KAUG];
__device__ __align__(256) __half g_LA[(size_t)ELCOL * KAUG];
__device__ __align__(256) float g_logits[T_TOK * NEXP];
__device__ __align__(256) float g_lowp[(size_t)KSPLIT1 * T_TOK * ELCOL];

// ---------------- helpers ----------------
__device__ __forceinline__ uint32_t smem_u32(const void* p) {
    uint32_t a;
    asm("{ .reg .u64 t; cvta.to.shared.u64 t, %1; cvt.u32.u64 %0, t; }"
        : "=r"(a) : "l"(p));
    return a;
}

__device__ __forceinline__ void cpasync16(uint32_t dst, const void* src) {
    asm volatile("cp.async.cg.shared.global [%0], [%1], 16;" :: "r"(dst), "l"(src) : "memory");
}

// SW128: for byte offsets with 128B rows this is seg16 ^= (row & 7)
#define SW128(o) ((o) ^ ((((uint32_t)(o)) >> 3) & 0x70u))

__device__ __forceinline__ void ldm_x4(uint32_t& r0, uint32_t& r1, uint32_t& r2, uint32_t& r3,
                                       uint32_t addr) {
    asm volatile("ldmatrix.sync.aligned.m8n8.x4.shared.b16 {%0,%1,%2,%3}, [%4];"
                 : "=r"(r0), "=r"(r1), "=r"(r2), "=r"(r3) : "r"(addr));
}

__device__ __forceinline__ void mma16816(float& d0, float& d1, float& d2, float& d3,
                                         uint32_t a0, uint32_t a1, uint32_t a2, uint32_t a3,
                                         uint32_t b0, uint32_t b1) {
    asm volatile(
        "mma.sync.aligned.m16n8k16.row.col.f32.f16.f16.f32 "
        "{%0,%1,%2,%3}, {%4,%5,%6,%7}, {%8,%9}, {%0,%1,%2,%3};"
        : "+f"(d0), "+f"(d1), "+f"(d2), "+f"(d3)
        : "r"(a0), "r"(a1), "r"(a2), "r"(a3), "r"(b0), "r"(b1));
}

// ---------------- convert kernels ----------------
__device__ __forceinline__ void split_store_h(float v, __half* hi, __half* lo, size_t idx) {
    __half h = __float2half(v);
    hi[idx] = h;
    lo[idx] = __float2half(v - __half2float(h));
}

// A-side: float4 -> fp16 hi x4 (8B) + fp16 lo x4 (8B)
__device__ __forceinline__ void split4_store_h(float4 v, __half* hi, __half* lo, size_t idx) {
    __half hx = __float2half(v.x), hy = __float2half(v.y);
    __half hz = __float2half(v.z), hw = __float2half(v.w);
    __half lx = __float2half(v.x - __half2float(hx));
    __half ly = __float2half(v.y - __half2float(hy));
    __half lz = __float2half(v.z - __half2float(hz));
    __half lw = __float2half(v.w - __half2float(hw));
    __half2 h01 = __halves2half2(hx, hy), h23 = __halves2half2(hz, hw);
    __half2 l01 = __halves2half2(lx, ly), l23 = __halves2half2(lz, lw);
    uint2 H, L;
    H.x = *reinterpret_cast<uint32_t*>(&h01); H.y = *reinterpret_cast<uint32_t*>(&h23);
    L.x = *reinterpret_cast<uint32_t*>(&l01); L.y = *reinterpret_cast<uint32_t*>(&l23);
    *reinterpret_cast<uint2*>(hi + idx) = H;
    *reinterpret_cast<uint2*>(lo + idx) = L;
}

// B-side: float4 -> fp16 x4 (8B)
__device__ __forceinline__ void conv4_store_h(float4 v, __half* dst, size_t idx) {
    __half2 h01 = __floats2half2_rn(v.x, v.y);
    __half2 h23 = __floats2half2_rn(v.z, v.w);
    uint2 H;
    H.x = *reinterpret_cast<uint32_t*>(&h01); H.y = *reinterpret_cast<uint32_t*>(&h23);
    *reinterpret_cast<uint2*>(dst + idx) = H;
}

__global__ void k_convert_x(const float* __restrict__ x) {
    size_t stride = (size_t)gridDim.x * blockDim.x;
    const size_t N4 = (size_t)T_TOK * D_K / 4;
    for (size_t i = (size_t)blockIdx.x * blockDim.x + threadIdx.x; i < N4; i += stride) {
        size_t base = i * 4;
        size_t t = base >> 12, k = base & 4095;
        split4_store_h(((const float4*)x)[i], g_XA_hi, g_XA_lo, t * KAUG + k);
    }
}

__global__ void k_convert_w(const float* __restrict__ bw, const float* __restrict__ lb) {
    size_t stride = (size_t)gridDim.x * blockDim.x;
    const size_t N1_4 = (size_t)D_O * D_K / 4;             // base_w in float4s
    const size_t N2_4 = (size_t)NEXP * D_O * 16 / 4;       // lora_B [E, O, R] in float4s
    for (size_t i = (size_t)blockIdx.x * blockDim.x + threadIdx.x;
         i < N1_4 + N2_4; i += stride) {
        if (i < N1_4) {
            size_t base = i * 4;
            size_t o = base >> 12, k = base & 4095;
            conv4_store_h(((const float4*)bw)[i], g_WB, o * KAUG + k);
        } else {
            size_t j = (i - N1_4) * 4;                     // element index in lora_B
            size_t e = j >> 16;                            // 4096*16 per expert
            size_t rem = j & 65535;
            size_t o = rem >> 4, r = rem & 15;             // r multiple of 4
            conv4_store_h(((const float4*)lb)[i - N1_4],
                          g_WB, o * KAUG + D_K + e * 16 + r);
        }
    }
}

__global__ void k_convert_la(const float* __restrict__ la) {
    size_t stride = (size_t)gridDim.x * blockDim.x;
    const size_t N4 = (size_t)ELCOL * D_K / 4;
    for (size_t i = (size_t)blockIdx.x * blockDim.x + threadIdx.x; i < N4; i += stride) {
        size_t base = i * 4;
        size_t row = base >> 12, k = base & 4095;
        conv4_store_h(((const float4*)la)[i], g_LA, row * KAUG + k);
    }
}

// ---------------- gate: exact fp32 logits, one warp per token, 2-way ILP ----------------
__global__ void k_gate(const float* __restrict__ x, const float* __restrict__ gw) {
    int warp = (int)((blockIdx.x * blockDim.x + threadIdx.x) >> 5);
    int lane = threadIdx.x & 31;
    if (warp >= T_TOK) return;
    const float4* xp = (const float4*)(x + (size_t)warp * D_K);
    const float4* gp = (const float4*)gw;
    float acc0[NEXP], acc1[NEXP];
#pragma unroll
    for (int e = 0; e < NEXP; e++) { acc0[e] = 0.f; acc1[e] = 0.f; }
    for (int j = 0; j < 32; j += 2) {
        int i0 = j * 32 + lane;
        int i1 = i0 + 32;
        float4 xv0 = xp[i0];
        float4 xv1 = xp[i1];
#pragma unroll
        for (int e = 0; e < NEXP; e++) {
            float4 g0 = gp[e * 1024 + i0];
            float4 g1 = gp[e * 1024 + i1];
            acc0[e] += xv0.x * g0.x + xv0.y * g0.y + xv0.z * g0.z + xv0.w * g0.w;
            acc1[e] += xv1.x * g1.x + xv1.y * g1.y + xv1.z * g1.z + xv1.w * g1.w;
        }
    }
#pragma unroll
    for (int e = 0; e < NEXP; e++) {
        float v = acc0[e] + acc1[e];
#pragma unroll
        for (int o = 16; o; o >>= 1) v += __shfl_xor_sync(0xffffffffu, v, o);
        if (lane == 0) g_logits[warp * NEXP + e] = v;
    }
}

// ---------------- routing: top-2 + softmax, reduce split-K partials, build U ----------------
__global__ void k_route() {
    int t = (int)((blockIdx.x * blockDim.x + threadIdx.x) >> 5);
    int lane = threadIdx.x & 31;
    if (t >= T_TOK) return;
    int i1 = 0, i2 = 0;
    float w1 = 0.f, w2 = 0.f;
    if (lane == 0) {
        float m1 = -1e30f, m2 = -1e30f;
#pragma unroll
        for (int e = 0; e < NEXP; e++) {
            float v = g_logits[t * NEXP + e];
            if (v > m1) { m2 = m1; i2 = i1; m1 = v; i1 = e; }
            else if (v > m2) { m2 = v; i2 = e; }
        }
        float s2 = expf(m2 - m1);
        w1 = 1.f / (1.f + s2);
        w2 = s2 * w1;
    }
    i1 = __shfl_sync(0xffffffffu, i1, 0);
    i2 = __shfl_sync(0xffffffffu, i2, 0);
    w1 = __shfl_sync(0xffffffffu, w1, 0);
    w2 = __shfl_sync(0xffffffffu, w2, 0);
    const size_t PS = (size_t)T_TOK * ELCOL;
#pragma unroll
    for (int j = 0; j < 4; j++) {
        int col = j * 32 + lane;
        int e = col >> 4;
        float wv = (e == i1) ? SCALING * w1 : (e == i2) ? SCALING * w2 : 0.f;
        float low = 0.f;
#pragma unroll
        for (int pz = 0; pz < KSPLIT1; pz++)
            low += g_lowp[pz * PS + (size_t)t * ELCOL + col];
        split_store_h(wv * low, g_XA_hi, g_XA_lo, (size_t)t * KAUG + D_K + col);
    }
}

// ---------------- 2-term fp16 mma.sync GEMM ----------------
// C[m, n] = sum_k (Ahi+Alo)[m,k] * B[n,k]  (2 mma terms), + bias[n]
// A split fp16 pair, B single fp16. K-major (ld = KAUG).
// CTA tile 128x128, BK=64, 4-stage cp.async pipeline (48 KB/stage).
// blockIdx.z = split-K slice: chunks [z*nChunks, (z+1)*nChunks), C += z*strideZ.
#define STAGES 4
#define BK 64
#define STAGE_BYTES 49152           // Ahi|Alo|B, each 128 rows x 128B
#define A_HI_OFF 0
#define A_LO_OFF 16384
#define B_OFF    32768
#define SMEM_TOTAL (STAGES * STAGE_BYTES)   // 192 KB (epilogue reuses)
#define EPI_PITCH 132

struct GemmPtrs {
    const __half *Ahi, *Alo, *B;
};

__device__ __forceinline__ void load_chunk(
    uint32_t sb, int tid, int m0, int n0, int stage, size_t kb, const GemmPtrs p)
{
    const uint32_t base = sb + (uint32_t)(stage * STAGE_BYTES);
#pragma unroll
    for (int pass = 0; pass < 4; pass++) {
        const int i = pass * 256 + tid;       // 0..1023
        const int row = i >> 3;
        const int seg = i & 7;
        const uint32_t so = SW128((uint32_t)(row * 128 + seg * 16));
        const size_t ao = (size_t)(m0 + row) * KAUG + kb + seg * 8;
        const size_t bo = (size_t)(n0 + row) * KAUG + kb + seg * 8;
        cpasync16(base + A_HI_OFF + so, p.Ahi + ao);
        cpasync16(base + A_LO_OFF + so, p.Alo + ao);
        cpasync16(base + B_OFF    + so, p.B   + bo);
    }
}

__global__ void __launch_bounds__(256, 1)
gemm_split(const __half* __restrict__ Ahi, const __half* __restrict__ Alo,
           const __half* __restrict__ B,
           float* __restrict__ C, const float* __restrict__ bias,
           int nChunks, int ldC, size_t strideZ)
{
    extern __shared__ char smem[];
    const uint32_t sb = smem_u32(smem);
    const int tid = threadIdx.x;
    const int wid = tid >> 5;
    const int lane = tid & 31;
    const int wm = wid & 1;          // 2 warp rows (64 m each)
    const int wn = wid >> 1;         // 4 warp cols (32 n each)
    const int m0 = blockIdx.x * 128;
    const int n0 = blockIdx.y * 128;
    const int kOff = blockIdx.z * nChunks;
    C += (size_t)blockIdx.z * strideZ;
    GemmPtrs p{Ahi, Alo, B};

    float acc[4][4][4];              // [mtile][ntile][frag]
#pragma unroll
    for (int i = 0; i < 4; i++)
#pragma unroll
        for (int j = 0; j < 4; j++)
#pragma unroll
            for (int k = 0; k < 4; k++) acc[i][j][k] = 0.f;

    // per-lane ldmatrix row/seg components (within a 16-row tile)
    const int a_row = lane & 15;                 // A: rows 0-15
    const int a_seg = lane >> 4;                 // A: k 16B half
    const int b_row = (lane & 7) + ((lane >> 4) << 3);   // B: n row 0-15
    const int b_seg = (lane >> 3) & 1;                   // B: k 16B half

    // prologue: stages 0..STAGES-2
#pragma unroll
    for (int c = 0; c < STAGES - 1; c++) {
        load_chunk(sb, tid, m0, n0, c, (size_t)(kOff + c) * BK, p);
        asm volatile("cp.async.commit_group;" ::: "memory");
    }

    for (int c = 0; c < nChunks; c++) {
        asm volatile("cp.async.wait_group %0;" :: "n"(STAGES - 2) : "memory");
        __syncthreads();

        // issue next loads first (overlap with compute)
        if (c + STAGES - 1 < nChunks)
            load_chunk(sb, tid, m0, n0, (c + STAGES - 1) % STAGES,
                       (size_t)(kOff + c + STAGES - 1) * BK, p);
        asm volatile("cp.async.commit_group;" ::: "memory");

        const uint32_t base = sb + (uint32_t)((c % STAGES) * STAGE_BYTES);
#pragma unroll
        for (int ks = 0; ks < BK / 16; ks++) {
            uint32_t ah[4][4], al[4][4];
#pragma unroll
            for (int mt = 0; mt < 4; mt++) {
                const int row = wm * 64 + mt * 16 + a_row;
                const uint32_t so = SW128((uint32_t)(row * 128 + (ks * 2 + a_seg) * 16));
                ldm_x4(ah[mt][0], ah[mt][1], ah[mt][2], ah[mt][3], base + A_HI_OFF + so);
                ldm_x4(al[mt][0], al[mt][1], al[mt][2], al[mt][3], base + A_LO_OFF + so);
            }
            uint32_t bh[2][4];
#pragma unroll
            for (int pr = 0; pr < 2; pr++) {
                const int row = wn * 32 + pr * 16 + b_row;
                const uint32_t so = SW128((uint32_t)(row * 128 + (ks * 2 + b_seg) * 16));
                ldm_x4(bh[pr][0], bh[pr][1], bh[pr][2], bh[pr][3], base + B_OFF + so);
            }
#pragma unroll
            for (int mt = 0; mt < 4; mt++) {
#pragma unroll
                for (int nt = 0; nt < 4; nt++) {
                    const int pr = nt >> 1, rb = (nt & 1) * 2;
                    float* d = acc[mt][nt];
                    mma16816(d[0], d[1], d[2], d[3],
                             ah[mt][0], ah[mt][1], ah[mt][2], ah[mt][3],
                             bh[pr][rb], bh[pr][rb + 1]);
                    mma16816(d[0], d[1], d[2], d[3],
                             al[mt][0], al[mt][1], al[mt][2], al[mt][3],
                             bh[pr][rb], bh[pr][rb + 1]);
                }
            }
        }
    }
    __syncthreads();

    // epilogue: frags -> smem (padded) -> coalesced global with fused bias
    float* smf = (float*)smem;
#pragma unroll
    for (int mt = 0; mt < 4; mt++) {
#pragma unroll
        for (int nt = 0; nt < 4; nt++) {
            const int row = wm * 64 + mt * 16 + (lane >> 2);
            const int col = wn * 32 + nt * 8 + (lane & 3) * 2;
            smf[row * EPI_PITCH + col]           = acc[mt][nt][0];
            smf[row * EPI_PITCH + col + 1]       = acc[mt][nt][1];
            smf[(row + 8) * EPI_PITCH + col]     = acc[mt][nt][2];
            smf[(row + 8) * EPI_PITCH + col + 1] = acc[mt][nt][3];
        }
    }
    __syncthreads();
    for (int i = tid; i < 128 * 128; i += 256) {
        const int r = i >> 7, col = i & 127;
        const float bv = bias ? bias[n0 + col] : 0.f;
        C[(size_t)(m0 + r) * ldC + n0 + col] = smf[r * EPI_PITCH + col] + bv;
    }
}

// ---------------- launch ----------------
extern "C" void kernel_launch(void* const* d_in, const int* in_sizes, int n_in,
                              void* d_out, int out_size) {
    const float* x  = (const float*)d_in[0];
    const float* gw = (const float*)d_in[1];
    const float* bw = (const float*)d_in[2];
    const float* bb = (const float*)d_in[3];
    const float* la = (const float*)d_in[4];
    const float* lb = (const float*)d_in[5];
    float* out = (float*)d_out;

    void *p_xahi, *p_xalo, *p_wb, *p_la, *p_lowp;
    cudaGetSymbolAddress(&p_xahi, g_XA_hi);
    cudaGetSymbolAddress(&p_xalo, g_XA_lo);
    cudaGetSymbolAddress(&p_wb,   g_WB);
    cudaGetSymbolAddress(&p_la,   g_LA);
    cudaGetSymbolAddress(&p_lowp, g_lowp);

    cudaFuncSetAttribute(gemm_split, cudaFuncAttributeMaxDynamicSharedMemorySize, SMEM_TOTAL);

    k_convert_x<<<2048, 256>>>(x);
    k_convert_w<<<2048, 256>>>(bw, lb);
    k_convert_la<<<256, 256>>>(la);
    k_gate<<<512, 256>>>(x, gw);

    // pass 1: low = X @ lora_A_cat^T   (M=4096, N=128, K=4096; split-K x4 -> 128 CTAs)
    gemm_split<<<dim3(32, 1, KSPLIT1), 256, SMEM_TOTAL>>>(
        (const __half*)p_xahi, (const __half*)p_xalo, (const __half*)p_la,
        (float*)p_lowp, nullptr, 64 / KSPLIT1, ELCOL, (size_t)T_TOK * ELCOL);

    k_route<<<1024, 128>>>();

    // pass 2: out = [X|U] @ [W|loraB]^T + b  (M=4096, N=4096, K=4224 -> 66 chunks)
    gemm_split<<<dim3(32, 32, 1), 256, SMEM_TOTAL>>>(
        (const __half*)p_xahi, (const __half*)p_xalo, (const __half*)p_wb,
        out, bb, 66, D_O, 0);
}

// round 17
// speedup vs baseline: 2.4367x; 1.5268x over previous
#include <cuda_runtime.h>
#include <cuda_fp16.h>
#include <cstdint>
#include <math.h>

// ---------------- problem constants ----------------
#define T_TOK 4096      // B*S tokens
#define D_K   4096      // d_in
#define KAUG  4224      // d_in + E*R augmented K
#define D_O   4096      // d_out
#define NEXP  8
#define ELCOL 128       // E*R
#define SCALING 2.0f
#define KSPLIT1 4       // pass-1 split-K factor

// ---------------- scratch (device globals; no allocation allowed) ----------------
// Both operands single fp16: per-side rounding 2^-11; measured one-sided global
// rel err = 2.09e-4, predicted two-sided = sqrt(2)x = ~3e-4 << 1e-3 gate.
__device__ __align__(256) __half g_XA[(size_t)T_TOK * KAUG];
__device__ __align__(256) __half g_WB[(size_t)D_O * KAUG];
__device__ __align__(256) __half g_LA[(size_t)ELCOL * KAUG];
__device__ __align__(256) float g_logits[T_TOK * NEXP];
__device__ __align__(256) float g_lowp[(size_t)KSPLIT1 * T_TOK * ELCOL];

// ---------------- helpers ----------------
__device__ __forceinline__ uint32_t smem_u32(const void* p) {
    uint32_t a;
    asm("{ .reg .u64 t; cvta.to.shared.u64 t, %1; cvt.u32.u64 %0, t; }"
        : "=r"(a) : "l"(p));
    return a;
}

__device__ __forceinline__ void cpasync16(uint32_t dst, const void* src) {
    asm volatile("cp.async.cg.shared.global [%0], [%1], 16;" :: "r"(dst), "l"(src) : "memory");
}

// SW128: for byte offsets with 128B rows this is seg16 ^= (row & 7)
#define SW128(o) ((o) ^ ((((uint32_t)(o)) >> 3) & 0x70u))

__device__ __forceinline__ void ldm_x4(uint32_t& r0, uint32_t& r1, uint32_t& r2, uint32_t& r3,
                                       uint32_t addr) {
    asm volatile("ldmatrix.sync.aligned.m8n8.x4.shared.b16 {%0,%1,%2,%3}, [%4];"
                 : "=r"(r0), "=r"(r1), "=r"(r2), "=r"(r3) : "r"(addr));
}

__device__ __forceinline__ void mma16816(float& d0, float& d1, float& d2, float& d3,
                                         uint32_t a0, uint32_t a1, uint32_t a2, uint32_t a3,
                                         uint32_t b0, uint32_t b1) {
    asm volatile(
        "mma.sync.aligned.m16n8k16.row.col.f32.f16.f16.f32 "
        "{%0,%1,%2,%3}, {%4,%5,%6,%7}, {%8,%9}, {%0,%1,%2,%3};"
        : "+f"(d0), "+f"(d1), "+f"(d2), "+f"(d3)
        : "r"(a0), "r"(a1), "r"(a2), "r"(a3), "r"(b0), "r"(b1));
}

// ---------------- convert kernels ----------------
// float4 -> fp16 x4 (8B vector store)
__device__ __forceinline__ void conv4_store_h(float4 v, __half* dst, size_t idx) {
    __half2 h01 = __floats2half2_rn(v.x, v.y);
    __half2 h23 = __floats2half2_rn(v.z, v.w);
    uint2 H;
    H.x = *reinterpret_cast<uint32_t*>(&h01); H.y = *reinterpret_cast<uint32_t*>(&h23);
    *reinterpret_cast<uint2*>(dst + idx) = H;
}

__global__ void k_convert_x(const float* __restrict__ x) {
    size_t stride = (size_t)gridDim.x * blockDim.x;
    const size_t N4 = (size_t)T_TOK * D_K / 4;
    for (size_t i = (size_t)blockIdx.x * blockDim.x + threadIdx.x; i < N4; i += stride) {
        size_t base = i * 4;
        size_t t = base >> 12, k = base & 4095;
        conv4_store_h(((const float4*)x)[i], g_XA, t * KAUG + k);
    }
}

__global__ void k_convert_w(const float* __restrict__ bw, const float* __restrict__ lb) {
    size_t stride = (size_t)gridDim.x * blockDim.x;
    const size_t N1_4 = (size_t)D_O * D_K / 4;             // base_w in float4s
    const size_t N2_4 = (size_t)NEXP * D_O * 16 / 4;       // lora_B [E, O, R] in float4s
    for (size_t i = (size_t)blockIdx.x * blockDim.x + threadIdx.x;
         i < N1_4 + N2_4; i += stride) {
        if (i < N1_4) {
            size_t base = i * 4;
            size_t o = base >> 12, k = base & 4095;
            conv4_store_h(((const float4*)bw)[i], g_WB, o * KAUG + k);
        } else {
            size_t j = (i - N1_4) * 4;                     // element index in lora_B
            size_t e = j >> 16;                            // 4096*16 per expert
            size_t rem = j & 65535;
            size_t o = rem >> 4, r = rem & 15;             // r multiple of 4
            conv4_store_h(((const float4*)lb)[i - N1_4],
                          g_WB, o * KAUG + D_K + e * 16 + r);
        }
    }
}

__global__ void k_convert_la(const float* __restrict__ la) {
    size_t stride = (size_t)gridDim.x * blockDim.x;
    const size_t N4 = (size_t)ELCOL * D_K / 4;
    for (size_t i = (size_t)blockIdx.x * blockDim.x + threadIdx.x; i < N4; i += stride) {
        size_t base = i * 4;
        size_t row = base >> 12, k = base & 4095;
        conv4_store_h(((const float4*)la)[i], g_LA, row * KAUG + k);
    }
}

// ---------------- gate: exact fp32 logits, one warp per token, 2-way ILP ----------------
__global__ void k_gate(const float* __restrict__ x, const float* __restrict__ gw) {
    int warp = (int)((blockIdx.x * blockDim.x + threadIdx.x) >> 5);
    int lane = threadIdx.x & 31;
    if (warp >= T_TOK) return;
    const float4* xp = (const float4*)(x + (size_t)warp * D_K);
    const float4* gp = (const float4*)gw;
    float acc0[NEXP], acc1[NEXP];
#pragma unroll
    for (int e = 0; e < NEXP; e++) { acc0[e] = 0.f; acc1[e] = 0.f; }
    for (int j = 0; j < 32; j += 2) {
        int i0 = j * 32 + lane;
        int i1 = i0 + 32;
        float4 xv0 = xp[i0];
        float4 xv1 = xp[i1];
#pragma unroll
        for (int e = 0; e < NEXP; e++) {
            float4 g0 = gp[e * 1024 + i0];
            float4 g1 = gp[e * 1024 + i1];
            acc0[e] += xv0.x * g0.x + xv0.y * g0.y + xv0.z * g0.z + xv0.w * g0.w;
            acc1[e] += xv1.x * g1.x + xv1.y * g1.y + xv1.z * g1.z + xv1.w * g1.w;
        }
    }
#pragma unroll
    for (int e = 0; e < NEXP; e++) {
        float v = acc0[e] + acc1[e];
#pragma unroll
        for (int o = 16; o; o >>= 1) v += __shfl_xor_sync(0xffffffffu, v, o);
        if (lane == 0) g_logits[warp * NEXP + e] = v;
    }
}

// ---------------- routing: top-2 + softmax, reduce split-K partials, build U ----------------
__global__ void k_route() {
    int t = (int)((blockIdx.x * blockDim.x + threadIdx.x) >> 5);
    int lane = threadIdx.x & 31;
    if (t >= T_TOK) return;
    int i1 = 0, i2 = 0;
    float w1 = 0.f, w2 = 0.f;
    if (lane == 0) {
        float m1 = -1e30f, m2 = -1e30f;
#pragma unroll
        for (int e = 0; e < NEXP; e++) {
            float v = g_logits[t * NEXP + e];
            if (v > m1) { m2 = m1; i2 = i1; m1 = v; i1 = e; }
            else if (v > m2) { m2 = v; i2 = e; }
        }
        float s2 = expf(m2 - m1);
        w1 = 1.f / (1.f + s2);
        w2 = s2 * w1;
    }
    i1 = __shfl_sync(0xffffffffu, i1, 0);
    i2 = __shfl_sync(0xffffffffu, i2, 0);
    w1 = __shfl_sync(0xffffffffu, w1, 0);
    w2 = __shfl_sync(0xffffffffu, w2, 0);
    const size_t PS = (size_t)T_TOK * ELCOL;
#pragma unroll
    for (int j = 0; j < 4; j++) {
        int col = j * 32 + lane;
        int e = col >> 4;
        float wv = (e == i1) ? SCALING * w1 : (e == i2) ? SCALING * w2 : 0.f;
        float low = 0.f;
#pragma unroll
        for (int pz = 0; pz < KSPLIT1; pz++)
            low += g_lowp[pz * PS + (size_t)t * ELCOL + col];
        g_XA[(size_t)t * KAUG + D_K + col] = __float2half(wv * low);
    }
}

// ---------------- single-fp16 mma.sync GEMM ----------------
// C[m, n] = sum_k A[m,k] * B[n,k] + bias[n].  A, B fp16, K-major (ld = KAUG).
// CTA tile 128x128, BK=64, 5-stage cp.async pipeline (32 KB/stage).
// blockIdx.z = split-K slice: chunks [z*nChunks, (z+1)*nChunks), C += z*strideZ.
#define STAGES 5
#define BK 64
#define STAGE_BYTES 32768           // A|B, each 128 rows x 128B
#define A_OFF 0
#define B_OFF 16384
#define SMEM_TOTAL (STAGES * STAGE_BYTES)   // 160 KB (epilogue reuses 67.6 KB)
#define EPI_PITCH 132

struct GemmPtrs {
    const __half *A, *B;
};

__device__ __forceinline__ void load_chunk(
    uint32_t sb, int tid, int m0, int n0, int stage, size_t kb, const GemmPtrs p)
{
    const uint32_t base = sb + (uint32_t)(stage * STAGE_BYTES);
#pragma unroll
    for (int pass = 0; pass < 4; pass++) {
        const int i = pass * 256 + tid;       // 0..1023
        const int row = i >> 3;
        const int seg = i & 7;
        const uint32_t so = SW128((uint32_t)(row * 128 + seg * 16));
        const size_t ao = (size_t)(m0 + row) * KAUG + kb + seg * 8;
        const size_t bo = (size_t)(n0 + row) * KAUG + kb + seg * 8;
        cpasync16(base + A_OFF + so, p.A + ao);
        cpasync16(base + B_OFF + so, p.B + bo);
    }
}

__global__ void __launch_bounds__(256, 1)
gemm_f16(const __half* __restrict__ A, const __half* __restrict__ B,
         float* __restrict__ C, const float* __restrict__ bias,
         int nChunks, int ldC, size_t strideZ)
{
    extern __shared__ char smem[];
    const uint32_t sb = smem_u32(smem);
    const int tid = threadIdx.x;
    const int wid = tid >> 5;
    const int lane = tid & 31;
    const int wm = wid & 1;          // 2 warp rows (64 m each)
    const int wn = wid >> 1;         // 4 warp cols (32 n each)
    const int m0 = blockIdx.x * 128;
    const int n0 = blockIdx.y * 128;
    const int kOff = blockIdx.z * nChunks;
    C += (size_t)blockIdx.z * strideZ;
    GemmPtrs p{A, B};

    float acc[4][4][4];              // [mtile][ntile][frag]
#pragma unroll
    for (int i = 0; i < 4; i++)
#pragma unroll
        for (int j = 0; j < 4; j++)
#pragma unroll
            for (int k = 0; k < 4; k++) acc[i][j][k] = 0.f;

    // per-lane ldmatrix row/seg components (within a 16-row tile)
    const int a_row = lane & 15;                 // A: rows 0-15
    const int a_seg = lane >> 4;                 // A: k 16B half
    const int b_row = (lane & 7) + ((lane >> 4) << 3);   // B: n row 0-15
    const int b_seg = (lane >> 3) & 1;                   // B: k 16B half

    // prologue: stages 0..STAGES-2
#pragma unroll
    for (int c = 0; c < STAGES - 1; c++) {
        load_chunk(sb, tid, m0, n0, c, (size_t)(kOff + c) * BK, p);
        asm volatile("cp.async.commit_group;" ::: "memory");
    }

    for (int c = 0; c < nChunks; c++) {
        asm volatile("cp.async.wait_group %0;" :: "n"(STAGES - 2) : "memory");
        __syncthreads();

        // issue next loads first (overlap with compute)
        if (c + STAGES - 1 < nChunks)
            load_chunk(sb, tid, m0, n0, (c + STAGES - 1) % STAGES,
                       (size_t)(kOff + c + STAGES - 1) * BK, p);
        asm volatile("cp.async.commit_group;" ::: "memory");

        const uint32_t base = sb + (uint32_t)((c % STAGES) * STAGE_BYTES);
#pragma unroll
        for (int ks = 0; ks < BK / 16; ks++) {
            uint32_t ah[4][4];
#pragma unroll
            for (int mt = 0; mt < 4; mt++) {
                const int row = wm * 64 + mt * 16 + a_row;
                const uint32_t so = SW128((uint32_t)(row * 128 + (ks * 2 + a_seg) * 16));
                ldm_x4(ah[mt][0], ah[mt][1], ah[mt][2], ah[mt][3], base + A_OFF + so);
            }
            uint32_t bh[2][4];
#pragma unroll
            for (int pr = 0; pr < 2; pr++) {
                const int row = wn * 32 + pr * 16 + b_row;
                const uint32_t so = SW128((uint32_t)(row * 128 + (ks * 2 + b_seg) * 16));
                ldm_x4(bh[pr][0], bh[pr][1], bh[pr][2], bh[pr][3], base + B_OFF + so);
            }
#pragma unroll
            for (int mt = 0; mt < 4; mt++) {
#pragma unroll
                for (int nt = 0; nt < 4; nt++) {
                    const int pr = nt >> 1, rb = (nt & 1) * 2;
                    float* d = acc[mt][nt];
                    mma16816(d[0], d[1], d[2], d[3],
                             ah[mt][0], ah[mt][1], ah[mt][2], ah[mt][3],
                             bh[pr][rb], bh[pr][rb + 1]);
                }
            }
        }
    }
    __syncthreads();

    // epilogue: frags -> smem (padded) -> coalesced global with fused bias
    float* smf = (float*)smem;
#pragma unroll
    for (int mt = 0; mt < 4; mt++) {
#pragma unroll
        for (int nt = 0; nt < 4; nt++) {
            const int row = wm * 64 + mt * 16 + (lane >> 2);
            const int col = wn * 32 + nt * 8 + (lane & 3) * 2;
            smf[row * EPI_PITCH + col]           = acc[mt][nt][0];
            smf[row * EPI_PITCH + col + 1]       = acc[mt][nt][1];
            smf[(row + 8) * EPI_PITCH + col]     = acc[mt][nt][2];
            smf[(row + 8) * EPI_PITCH + col + 1] = acc[mt][nt][3];
        }
    }
    __syncthreads();
    for (int i = tid; i < 128 * 128; i += 256) {
        const int r = i >> 7, col = i & 127;
        const float bv = bias ? bias[n0 + col] : 0.f;
        C[(size_t)(m0 + r) * ldC + n0 + col] = smf[r * EPI_PITCH + col] + bv;
    }
}

// ---------------- launch ----------------
extern "C" void kernel_launch(void* const* d_in, const int* in_sizes, int n_in,
                              void* d_out, int out_size) {
    const float* x  = (const float*)d_in[0];
    const float* gw = (const float*)d_in[1];
    const float* bw = (const float*)d_in[2];
    const float* bb = (const float*)d_in[3];
    const float* la = (const float*)d_in[4];
    const float* lb = (const float*)d_in[5];
    float* out = (float*)d_out;

    void *p_xa, *p_wb, *p_la, *p_lowp;
    cudaGetSymbolAddress(&p_xa,   g_XA);
    cudaGetSymbolAddress(&p_wb,   g_WB);
    cudaGetSymbolAddress(&p_la,   g_LA);
    cudaGetSymbolAddress(&p_lowp, g_lowp);

    cudaFuncSetAttribute(gemm_f16, cudaFuncAttributeMaxDynamicSharedMemorySize, SMEM_TOTAL);

    k_convert_x<<<2048, 256>>>(x);
    k_convert_w<<<2048, 256>>>(bw, lb);
    k_convert_la<<<256, 256>>>(la);
    k_gate<<<512, 256>>>(x, gw);

    // pass 1: low = X @ lora_A_cat^T   (M=4096, N=128, K=4096; split-K x4 -> 128 CTAs)
    gemm_f16<<<dim3(32, 1, KSPLIT1), 256, SMEM_TOTAL>>>(
        (const __half*)p_xa, (const __half*)p_la,
        (float*)p_lowp, nullptr, 64 / KSPLIT1, ELCOL, (size_t)T_TOK * ELCOL);

    k_route<<<1024, 128>>>();

    // pass 2: out = [X|U] @ [W|loraB]^T + b  (M=4096, N=4096, K=4224 -> 66 chunks)
    gemm_f16<<<dim3(32, 32, 1), 256, SMEM_TOTAL>>>(
        (const __half*)p_xa, (const __half*)p_wb,
        out, bb, 66, D_O, 0);
}